// round 2
// baseline (speedup 1.0000x reference)
#include <cuda_runtime.h>
#include <cstdint>
#include <cstddef>

#define G    512
#define NPG  512
#define D    128
#define A    16
#define NEGV -1000000000.0f

#define THREADS 128
#define CHUNK   128
#define NCHUNK  (NPG / CHUNK)
#define TS_F4   33          // tile row stride in float4 units (132 floats, pad for banks)
#define NW      34          // total weight rows: node(1) + an(16) + qn(1) + qan(16)

// ---- shared memory layout (in floats) ----
#define OFF_W     0                                   // 34*128 = 4352
#define OFF_TILE  (OFF_W + NW * D)                    // 4352  ; 128*132 = 16896
#define OFF_NLOG  (OFF_TILE + CHUNK * TS_F4 * 4)      // 21248 ; 512
#define OFF_HA    (OFF_NLOG + NPG)                    // 21760
#define OFF_QN    (OFF_HA + NPG)                      // 22272
#define OFF_QAD   (OFF_QN + NPG)                      // 22784
#define OFF_BIAS  (OFF_QAD + NPG)                     // 23296 ; 33 (pad 36)
#define OFF_RED   (OFF_BIAS + 36)                     // 23332 ; 8
#define OFF_SEL   (OFF_RED + 8)                       // 23340 ; 1 (+pad)
#define SMEM_FLOATS (OFF_SEL + 4)                     // 23344 -> 93376 bytes

__device__ __forceinline__ void fma2(unsigned long long &acc,
                                     unsigned long long a,
                                     unsigned long long b) {
    asm("fma.rn.f32x2 %0, %1, %2, %3;" : "=l"(acc) : "l"(a), "l"(b), "l"(acc));
}

__device__ __forceinline__ float hsum2(unsigned long long v) {
    float lo = __uint_as_float((unsigned)(v & 0xFFFFFFFFull));
    float hi = __uint_as_float((unsigned)(v >> 32));
    return lo + hi;
}

__device__ __forceinline__ float warpMax(float v) {
    #pragma unroll
    for (int o = 16; o > 0; o >>= 1) v = fmaxf(v, __shfl_xor_sync(0xffffffffu, v, o));
    return v;
}
__device__ __forceinline__ float warpSum(float v) {
    #pragma unroll
    for (int o = 16; o > 0; o >>= 1) v += __shfl_xor_sync(0xffffffffu, v, o);
    return v;
}

__global__ void __launch_bounds__(THREADS)
policy_kernel(const int* __restrict__ a,
              const float* __restrict__ h,
              const int* __restrict__ mask,          // int32 0/1, [N, A]
              const float* __restrict__ w_node,
              const float* __restrict__ w_an,
              const float* __restrict__ b_an,
              const float* __restrict__ w_qn,
              const float* __restrict__ b_qn,
              const float* __restrict__ w_qan,
              const float* __restrict__ b_qan,
              float* __restrict__ out)
{
    extern __shared__ float sm[];
    const int tid   = threadIdx.x;
    const int g     = blockIdx.x;
    const int gbase = g * NPG;

    // ---- stage weights: row 0 = w_node, 1..16 = w_an, 17 = w_qn, 18..33 = w_qan
    for (int idx = tid; idx < NW * D; idx += THREADS) {
        int r = idx >> 7, k = idx & 127;
        float v;
        if      (r == 0)  v = w_node[k];
        else if (r <= 16) v = w_an[(r - 1) * D + k];
        else if (r == 17) v = w_qn[k];
        else              v = w_qan[(r - 18) * D + k];
        sm[OFF_W + idx] = v;
    }
    if      (tid < 16)  sm[OFF_BIAS + tid] = b_an[tid];
    else if (tid < 32)  sm[OFF_BIAS + tid] = b_qan[tid - 16];
    else if (tid == 32) sm[OFF_BIAS + 32]  = b_qn[0];
    if (tid == 0) sm[OFF_SEL] = 0.0f;

    const int sel_act  = a[2 * g];
    const int sel_node = a[2 * g + 1];

    const ulonglong2* wU = reinterpret_cast<const ulonglong2*>(&sm[OFF_W]);
    ulonglong2*       tU = reinterpret_cast<ulonglong2*>(&sm[OFF_TILE]);
    float4*      tileF4  = reinterpret_cast<float4*>(&sm[OFF_TILE]);
    const float4*    h4  = reinterpret_cast<const float4*>(h);

    for (int c = 0; c < NCHUNK; c++) {
        __syncthreads();   // previous chunk's compute done before overwrite
        const int cb = gbase + c * CHUNK;

        // ---- coalesced tile load: CHUNK rows x 32 float4
        for (int idx = tid; idx < CHUNK * 32; idx += THREADS) {
            int row = idx >> 5, kv = idx & 31;
            tileF4[row * TS_F4 + kv] = h4[(size_t)(cb + row) * 32 + kv];
        }
        __syncthreads();

        const int node = cb + tid;
        const ulonglong2* myrow = tU + tid * TS_F4;

        unsigned long long acc[NW];
        #pragma unroll
        for (int j = 0; j < NW; j++) acc[j] = 0ull;

        #pragma unroll 4
        for (int kv = 0; kv < 32; kv++) {
            ulonglong2 hv = myrow[kv];
            #pragma unroll
            for (int j = 0; j < NW; j++) {
                ulonglong2 wv = wU[j * 32 + kv];
                fma2(acc[j], hv.x, wv.x);
                fma2(acc[j], hv.y, wv.y);
            }
        }

        // ---- per-node epilogue
        // action_mask materialized as int32 [N, A]: 16 ints = 4 x int4
        const int4* m4 = reinterpret_cast<const int4*>(mask + (size_t)node * A);
        int mv[A];
        #pragma unroll
        for (int q = 0; q < 4; q++) {
            int4 mq = m4[q];
            mv[q * 4 + 0] = mq.x; mv[q * 4 + 1] = mq.y;
            mv[q * 4 + 2] = mq.z; mv[q * 4 + 3] = mq.w;
        }

        float nodelog = hsum2(acc[0]);
        float qn      = hsum2(acc[17]) + sm[OFF_BIAS + 32];

        float alog[A], qa[A];
        float mx = -3.0e38f;
        #pragma unroll
        for (int j = 0; j < A; j++) {
            float l = hsum2(acc[1 + j]) + sm[OFF_BIAS + j];
            alog[j] = (mv[j] != 0) ? l : NEGV;
            qa[j]   = hsum2(acc[18 + j]) + sm[OFF_BIAS + 16 + j];
            mx = fmaxf(mx, alog[j]);
        }
        float e[A];
        float se = 0.0f;
        #pragma unroll
        for (int j = 0; j < A; j++) { e[j] = expf(alog[j] - mx); se += e[j]; }
        float lse = mx + logf(se);
        float inv = 1.0f / se;
        float ha = 0.0f, qad = 0.0f;
        #pragma unroll
        for (int j = 0; j < A; j++) {
            float p  = e[j] * inv;
            float lp = alog[j] - lse;
            ha  -= p * lp;
            qad += qa[j] * p;
        }
        int nm = 0;
        #pragma unroll
        for (int j = 1; j < A; j++) nm |= mv[j];
        bool nmask = (nm != 0);

        int li = c * CHUNK + tid;
        sm[OFF_NLOG + li] = nmask ? nodelog : NEGV;
        sm[OFF_HA   + li] = ha;
        sm[OFF_QN   + li] = qn;
        sm[OFF_QAD  + li] = qad;
        if (node == sel_node) sm[OFF_SEL] = alog[sel_act] - lse;
    }
    __syncthreads();

    const int wid = tid >> 5, lid = tid & 31;

    // ---- group max of node logits
    float v = -3.0e38f;
    #pragma unroll
    for (int i = 0; i < 4; i++) v = fmaxf(v, sm[OFF_NLOG + tid + i * THREADS]);
    v = warpMax(v);
    if (lid == 0) sm[OFF_RED + wid] = v;
    __syncthreads();
    float M = fmaxf(fmaxf(sm[OFF_RED + 0], sm[OFF_RED + 1]),
                    fmaxf(sm[OFF_RED + 2], sm[OFF_RED + 3]));
    __syncthreads();

    // ---- group sum of exp
    float s = 0.0f;
    #pragma unroll
    for (int i = 0; i < 4; i++) s += expf(sm[OFF_NLOG + tid + i * THREADS] - M);
    s = warpSum(s);
    if (lid == 0) sm[OFF_RED + wid] = s;
    __syncthreads();
    float Z = sm[OFF_RED + 0] + sm[OFF_RED + 1] + sm[OFF_RED + 2] + sm[OFF_RED + 3];
    float cns = M + logf(Z);
    __syncthreads();

    // ---- entropy & value sums
    float ent = 0.0f, val = 0.0f;
    #pragma unroll
    for (int i = 0; i < 4; i++) {
        int   idx = tid + i * THREADS;
        float nl  = sm[OFF_NLOG + idx];
        float lpn = nl - cns;
        float pn  = expf(lpn);
        ent += pn * (sm[OFF_HA + idx] - lpn);
        val += pn * sm[OFF_QN + idx];
    }
    ent = warpSum(ent);
    val = warpSum(val);
    if (lid == 0) { sm[OFF_RED + wid] = ent; sm[OFF_RED + 4 + wid] = val; }
    __syncthreads();

    if (tid == 0) {
        float ent_t = sm[OFF_RED + 0] + sm[OFF_RED + 1] + sm[OFF_RED + 2] + sm[OFF_RED + 3];
        float val_t = sm[OFF_RED + 4] + sm[OFF_RED + 5] + sm[OFF_RED + 6] + sm[OFF_RED + 7];
        int sl = sel_node - gbase;
        if (sl < 0) sl = 0;
        if (sl >= NPG) sl = NPG - 1;
        float lpn_sel = sm[OFF_NLOG + sl] - cns;
        out[g]         = lpn_sel + sm[OFF_SEL];   // logprob
        out[G + g]     = ent_t;                   // entropy
        out[2 * G + g] = val_t + sm[OFF_QAD + sl];// value
    }
}

extern "C" void kernel_launch(void* const* d_in, const int* in_sizes, int n_in,
                              void* d_out, int out_size)
{
    const int*   a       = (const int*)d_in[0];
    const float* h       = (const float*)d_in[1];
    const int*   mask    = (const int*)d_in[2];
    // d_in[3] = batch_idx (unused: segments are contiguous blocks of NPG)
    // d_in[4] = n_nodes   (unused: always NPG)
    const float* w_node  = (const float*)d_in[5];
    const float* w_an    = (const float*)d_in[6];
    const float* b_an    = (const float*)d_in[7];
    const float* w_qn    = (const float*)d_in[8];
    const float* b_qn    = (const float*)d_in[9];
    const float* w_qan   = (const float*)d_in[10];
    const float* b_qan   = (const float*)d_in[11];
    float*       out     = (float*)d_out;

    const size_t smem = SMEM_FLOATS * sizeof(float);
    cudaFuncSetAttribute(policy_kernel,
                         cudaFuncAttributeMaxDynamicSharedMemorySize, (int)smem);
    policy_kernel<<<G, THREADS, smem>>>(a, h, mask, w_node, w_an, b_an,
                                        w_qn, b_qn, w_qan, b_qan, out);
}

// round 3
// speedup vs baseline: 1.0030x; 1.0030x over previous
#include <cuda_runtime.h>
#include <cstdint>
#include <cstddef>

#define G    512
#define NPG  512
#define D    128
#define A    16
#define NEGV -1000000000.0f

#define THREADS 128
#define CHUNK   128
#define NCHUNK  (NPG / CHUNK)
#define TS_F4   33          // tile row stride in float4 units (132 floats, pad for banks)
#define NW      34          // total weight rows: node(1) + an(16) + qn(1) + qan(16)

// ---- shared memory layout (in floats) ----
#define OFF_W     0                                   // 34*128 = 4352
#define OFF_TILE  (OFF_W + NW * D)                    // 4352  ; 128*132 = 16896
#define OFF_NLOG  (OFF_TILE + CHUNK * TS_F4 * 4)      // 21248 ; 512
#define OFF_HA    (OFF_NLOG + NPG)                    // 21760
#define OFF_QN    (OFF_HA + NPG)                      // 22272
#define OFF_QAD   (OFF_QN + NPG)                      // 22784
#define OFF_BIAS  (OFF_QAD + NPG)                     // 23296 ; 33 (pad 36)
#define OFF_RED   (OFF_BIAS + 36)                     // 23332 ; 8
#define OFF_SEL   (OFF_RED + 8)                       // 23340 ; 1 (+pad)
#define SMEM_FLOATS (OFF_SEL + 4)                     // 23344 -> 93376 bytes

__device__ __forceinline__ void fma2(unsigned long long &acc,
                                     unsigned long long a,
                                     unsigned long long b) {
    asm("fma.rn.f32x2 %0, %1, %2, %3;" : "=l"(acc) : "l"(a), "l"(b), "l"(acc));
}

__device__ __forceinline__ float hsum2(unsigned long long v) {
    float lo = __uint_as_float((unsigned)(v & 0xFFFFFFFFull));
    float hi = __uint_as_float((unsigned)(v >> 32));
    return lo + hi;
}

__device__ __forceinline__ float warpMax(float v) {
    #pragma unroll
    for (int o = 16; o > 0; o >>= 1) v = fmaxf(v, __shfl_xor_sync(0xffffffffu, v, o));
    return v;
}
__device__ __forceinline__ float warpSum(float v) {
    #pragma unroll
    for (int o = 16; o > 0; o >>= 1) v += __shfl_xor_sync(0xffffffffu, v, o);
    return v;
}

__global__ void __launch_bounds__(THREADS)
policy_kernel(const int* __restrict__ a,
              const float* __restrict__ h,
              const int* __restrict__ mask,          // int32 0/1, [N, A]
              const float* __restrict__ w_node,
              const float* __restrict__ w_an,
              const float* __restrict__ b_an,
              const float* __restrict__ w_qn,
              const float* __restrict__ b_qn,
              const float* __restrict__ w_qan,
              const float* __restrict__ b_qan,
              float* __restrict__ out)
{
    extern __shared__ float sm[];
    const int tid   = threadIdx.x;
    const int g     = blockIdx.x;
    const int gbase = g * NPG;

    // ---- stage weights: row 0 = w_node, 1..16 = w_an, 17 = w_qn, 18..33 = w_qan
    for (int idx = tid; idx < NW * D; idx += THREADS) {
        int r = idx >> 7, k = idx & 127;
        float v;
        if      (r == 0)  v = w_node[k];
        else if (r <= 16) v = w_an[(r - 1) * D + k];
        else if (r == 17) v = w_qn[k];
        else              v = w_qan[(r - 18) * D + k];
        sm[OFF_W + idx] = v;
    }
    if      (tid < 16)  sm[OFF_BIAS + tid] = b_an[tid];
    else if (tid < 32)  sm[OFF_BIAS + tid] = b_qan[tid - 16];
    else if (tid == 32) sm[OFF_BIAS + 32]  = b_qn[0];
    if (tid == 0) sm[OFF_SEL] = 0.0f;

    const int sel_act  = a[2 * g];
    const int sel_node = a[2 * g + 1];

    const ulonglong2* wU = reinterpret_cast<const ulonglong2*>(&sm[OFF_W]);
    ulonglong2*       tU = reinterpret_cast<ulonglong2*>(&sm[OFF_TILE]);
    float4*      tileF4  = reinterpret_cast<float4*>(&sm[OFF_TILE]);
    const float4*    h4  = reinterpret_cast<const float4*>(h);

    for (int c = 0; c < NCHUNK; c++) {
        __syncthreads();   // previous chunk's compute done before overwrite
        const int cb = gbase + c * CHUNK;

        // ---- coalesced tile load: CHUNK rows x 32 float4
        for (int idx = tid; idx < CHUNK * 32; idx += THREADS) {
            int row = idx >> 5, kv = idx & 31;
            tileF4[row * TS_F4 + kv] = h4[(size_t)(cb + row) * 32 + kv];
        }
        __syncthreads();

        const int node = cb + tid;
        const ulonglong2* myrow = tU + tid * TS_F4;

        unsigned long long acc[NW];
        #pragma unroll
        for (int j = 0; j < NW; j++) acc[j] = 0ull;

        #pragma unroll 4
        for (int kv = 0; kv < 32; kv++) {
            ulonglong2 hv = myrow[kv];
            #pragma unroll
            for (int j = 0; j < NW; j++) {
                ulonglong2 wv = wU[j * 32 + kv];
                fma2(acc[j], hv.x, wv.x);
                fma2(acc[j], hv.y, wv.y);
            }
        }

        // ---- per-node epilogue
        // action_mask materialized as int32 [N, A]: 16 ints = 4 x int4
        const int4* m4 = reinterpret_cast<const int4*>(mask + (size_t)node * A);
        int mv[A];
        #pragma unroll
        for (int q = 0; q < 4; q++) {
            int4 mq = m4[q];
            mv[q * 4 + 0] = mq.x; mv[q * 4 + 1] = mq.y;
            mv[q * 4 + 2] = mq.z; mv[q * 4 + 3] = mq.w;
        }

        float nodelog = hsum2(acc[0]);
        float qn      = hsum2(acc[17]) + sm[OFF_BIAS + 32];

        float alog[A], qa[A];
        float mx = -3.0e38f;
        #pragma unroll
        for (int j = 0; j < A; j++) {
            float l = hsum2(acc[1 + j]) + sm[OFF_BIAS + j];
            alog[j] = (mv[j] != 0) ? l : NEGV;
            qa[j]   = hsum2(acc[18 + j]) + sm[OFF_BIAS + 16 + j];
            mx = fmaxf(mx, alog[j]);
        }
        float e[A];
        float se = 0.0f;
        #pragma unroll
        for (int j = 0; j < A; j++) { e[j] = expf(alog[j] - mx); se += e[j]; }
        float lse = mx + logf(se);
        float inv = 1.0f / se;
        float ha = 0.0f, qad = 0.0f;
        #pragma unroll
        for (int j = 0; j < A; j++) {
            float p  = e[j] * inv;
            float lp = alog[j] - lse;
            ha  -= p * lp;
            qad += qa[j] * p;
        }
        int nm = 0;
        #pragma unroll
        for (int j = 1; j < A; j++) nm |= mv[j];
        bool nmask = (nm != 0);

        int li = c * CHUNK + tid;
        sm[OFF_NLOG + li] = nmask ? nodelog : NEGV;
        sm[OFF_HA   + li] = ha;
        sm[OFF_QN   + li] = qn;
        sm[OFF_QAD  + li] = qad;
        if (node == sel_node) sm[OFF_SEL] = alog[sel_act] - lse;
    }
    __syncthreads();

    const int wid = tid >> 5, lid = tid & 31;

    // ---- group max of node logits
    float v = -3.0e38f;
    #pragma unroll
    for (int i = 0; i < 4; i++) v = fmaxf(v, sm[OFF_NLOG + tid + i * THREADS]);
    v = warpMax(v);
    if (lid == 0) sm[OFF_RED + wid] = v;
    __syncthreads();
    float M = fmaxf(fmaxf(sm[OFF_RED + 0], sm[OFF_RED + 1]),
                    fmaxf(sm[OFF_RED + 2], sm[OFF_RED + 3]));
    __syncthreads();

    // ---- group sum of exp
    float s = 0.0f;
    #pragma unroll
    for (int i = 0; i < 4; i++) s += expf(sm[OFF_NLOG + tid + i * THREADS] - M);
    s = warpSum(s);
    if (lid == 0) sm[OFF_RED + wid] = s;
    __syncthreads();
    float Z = sm[OFF_RED + 0] + sm[OFF_RED + 1] + sm[OFF_RED + 2] + sm[OFF_RED + 3];
    float cns = M + logf(Z);
    __syncthreads();

    // ---- entropy & value sums
    float ent = 0.0f, val = 0.0f;
    #pragma unroll
    for (int i = 0; i < 4; i++) {
        int   idx = tid + i * THREADS;
        float nl  = sm[OFF_NLOG + idx];
        float lpn = nl - cns;
        float pn  = expf(lpn);
        ent += pn * (sm[OFF_HA + idx] - lpn);
        val += pn * sm[OFF_QN + idx];
    }
    ent = warpSum(ent);
    val = warpSum(val);
    if (lid == 0) { sm[OFF_RED + wid] = ent; sm[OFF_RED + 4 + wid] = val; }
    __syncthreads();

    if (tid == 0) {
        float ent_t = sm[OFF_RED + 0] + sm[OFF_RED + 1] + sm[OFF_RED + 2] + sm[OFF_RED + 3];
        float val_t = sm[OFF_RED + 4] + sm[OFF_RED + 5] + sm[OFF_RED + 6] + sm[OFF_RED + 7];
        int sl = sel_node - gbase;
        if (sl < 0) sl = 0;
        if (sl >= NPG) sl = NPG - 1;
        float lpn_sel = sm[OFF_NLOG + sl] - cns;
        out[g]         = lpn_sel + sm[OFF_SEL];   // logprob
        out[G + g]     = ent_t;                   // entropy
        out[2 * G + g] = val_t + sm[OFF_QAD + sl];// value
    }
}

extern "C" void kernel_launch(void* const* d_in, const int* in_sizes, int n_in,
                              void* d_out, int out_size)
{
    const int*   a       = (const int*)d_in[0];
    const float* h       = (const float*)d_in[1];
    const int*   mask    = (const int*)d_in[2];
    // d_in[3] = batch_idx (unused: segments are contiguous blocks of NPG)
    // d_in[4] = n_nodes   (unused: always NPG)
    const float* w_node  = (const float*)d_in[5];
    const float* w_an    = (const float*)d_in[6];
    const float* b_an    = (const float*)d_in[7];
    const float* w_qn    = (const float*)d_in[8];
    const float* b_qn    = (const float*)d_in[9];
    const float* w_qan   = (const float*)d_in[10];
    const float* b_qan   = (const float*)d_in[11];
    float*       out     = (float*)d_out;

    const size_t smem = SMEM_FLOATS * sizeof(float);
    cudaFuncSetAttribute(policy_kernel,
                         cudaFuncAttributeMaxDynamicSharedMemorySize, (int)smem);
    policy_kernel<<<G, THREADS, smem>>>(a, h, mask, w_node, w_an, b_an,
                                        w_qn, b_qn, w_qan, b_qan, out);
}